// round 14
// baseline (speedup 1.0000x reference)
#include <cuda_runtime.h>
#include <cuda_fp16.h>

#define BN   4096
#define LEN  60
#define TS   60
#define HD   256
#define ID   6
#define OD   6
#define GD   1024
#define ROWS 32
#define NTH  1024
#define KDI  272         // decoder input K padded to 17 tiles of 16
#define NCTA (BN / ROWS)
#define AST  36          // float stride of activation buffers [k][row]

typedef unsigned long long u64;

// ---------------- device scratch (allocation-free) ----------------
// Gate-interleaved fp16 weights: W[k][u*4+g] = W_orig[g*256+u][k]  (g: 0=i,1=f,2=g,3=o)
__device__ __align__(16) __half g_Wh_e_ih[16 * GD];    // k rows 6..15 zero
__device__ __align__(16) __half g_Wh_e_hh[HD * GD];
__device__ __align__(16) float  g_bg_e[GD];
__device__ __align__(16) __half g_Wh_d_ih[KDI * GD];   // k rows 262..271 zero
__device__ __align__(16) __half g_Wh_d_hh[HD * GD];
__device__ __align__(16) float  g_bg_d[GD];
__device__ __align__(16) __half g_l1Th[HD * HD];       // [k][u]
__device__ __align__(16) float  g_l2T[HD * OD];        // [u][o]  (f32: output layer)
__device__ __align__(16) float  g_attnT[262 * 60];     // [k][l]  (f32)
__device__ __align__(16) __half g_ench[(size_t)BN * LEN * HD];  // encoder outputs fp16

// ---------------- packed fp32x2 helpers ----------------
__device__ __forceinline__ u64 pack2(float v) {
    u64 r; asm("mov.b64 %0, {%1, %1};" : "=l"(r) : "f"(v)); return r;
}
__device__ __forceinline__ u64 pkf2(float a, float b) {
    u64 r; asm("mov.b64 %0, {%1, %2};" : "=l"(r) : "f"(a), "f"(b)); return r;
}
__device__ __forceinline__ u64 fma2(u64 a, u64 b, u64 c) {
    u64 d; asm("fma.rn.f32x2 %0, %1, %2, %3;" : "=l"(d) : "l"(a), "l"(b), "l"(c)); return d;
}
__device__ __forceinline__ float2 unpk(u64 v) {
    float2 f; asm("mov.b64 {%0, %1}, %2;" : "=f"(f.x), "=f"(f.y) : "l"(v)); return f;
}
__device__ __forceinline__ float sigmf(float x) { return 1.0f / (1.0f + __expf(-x)); }

__device__ __forceinline__ unsigned su32(const void* p) {
    unsigned a;
    asm("{ .reg .u64 t; cvta.to.shared.u64 t, %1; cvt.u32.u64 %0, t; }" : "=r"(a) : "l"(p));
    return a;
}
__device__ __forceinline__ void cp16(unsigned d, const void* s) {
    asm volatile("cp.async.cg.shared.global [%0], [%1], 16;" :: "r"(d), "l"(s));
}
__device__ __forceinline__ void cpcommit() { asm volatile("cp.async.commit_group;"); }
__device__ __forceinline__ void cpwait1()  { asm volatile("cp.async.wait_group 1;"); }
__device__ __forceinline__ void cpwait0()  { asm volatile("cp.async.wait_group 0;"); }

// copy one 32KB tile: each of 1024 threads moves 32B
__device__ __forceinline__ void cp_tile(unsigned dst_s, const __half* src, int t) {
    unsigned d = dst_s + (unsigned)(t * 32);
    const char* s = (const char*)src + t * 32;
    cp16(d, s); cp16(d + 16, s + 16);
    cpcommit();
}

// main-gemm tile: 16 k-rows (fp16 weights); thread owns unit u (cols 4u..4u+3), rows q*8..q*8+7
__device__ __forceinline__ void tile16(u64 acc[4][4], const float* __restrict__ Ak,
                                       const __half* __restrict__ buf, int u, int q) {
#pragma unroll
    for (int kk = 0; kk < 16; kk++) {
        const __half2* wp = (const __half2*)&buf[kk * GD + 4 * u];
        __half2 w01 = wp[0], w23 = wp[1];
        float2 f01 = __half22float2(w01), f23 = __half22float2(w23);
        u64 b0 = pack2(f01.x), b1 = pack2(f01.y), b2 = pack2(f23.x), b3 = pack2(f23.y);
        const ulonglong2* ap = (const ulonglong2*)(Ak + kk * AST) + q * 2;
        ulonglong2 a01 = ap[0], a23 = ap[1];
        u64 av0 = a01.x, av1 = a01.y, av2 = a23.x, av3 = a23.y;
        acc[0][0] = fma2(av0, b0, acc[0][0]); acc[0][1] = fma2(av0, b1, acc[0][1]);
        acc[0][2] = fma2(av0, b2, acc[0][2]); acc[0][3] = fma2(av0, b3, acc[0][3]);
        acc[1][0] = fma2(av1, b0, acc[1][0]); acc[1][1] = fma2(av1, b1, acc[1][1]);
        acc[1][2] = fma2(av1, b2, acc[1][2]); acc[1][3] = fma2(av1, b3, acc[1][3]);
        acc[2][0] = fma2(av2, b0, acc[2][0]); acc[2][1] = fma2(av2, b1, acc[2][1]);
        acc[2][2] = fma2(av2, b2, acc[2][2]); acc[2][3] = fma2(av2, b3, acc[2][3]);
        acc[3][0] = fma2(av3, b0, acc[3][0]); acc[3][1] = fma2(av3, b1, acc[3][1]);
        acc[3][2] = fma2(av3, b2, acc[3][2]); acc[3][3] = fma2(av3, b3, acc[3][3]);
    }
}

// two-segment pipelined gemm (tiles of 16 k-rows x 1024 cols fp16, triple-buffered 32KB)
__device__ __forceinline__ void gemm_pipe(u64 acc[4][4],
        const __half* W0, const float* A0, int n0,
        const __half* W1, const float* A1, int n1,
        __half* wbuf, unsigned wbuf_s, int t, int u, int q) {
    const int NT = n0 + n1;
    cp_tile(wbuf_s, W0, t);
    {
        const __half* w1 = (1 < n0) ? (W0 + 16384) : (W1 + (1 - n0) * 16384);
        cp_tile(wbuf_s + 32768, w1, t);
    }
#pragma unroll 1
    for (int j = 0; j < NT; j++) {
        if (j + 1 < NT) cpwait1(); else cpwait0();
        __syncthreads();
        if (j + 2 < NT) {
            int jj = j + 2;
            const __half* ws = (jj < n0) ? (W0 + jj * 16384) : (W1 + (jj - n0) * 16384);
            cp_tile(wbuf_s + (unsigned)((jj % 3) * 32768), ws, t);
        }
        const float* Ak = (j < n0) ? (A0 + j * 16 * AST) : (A1 + (j - n0) * 16 * AST);
        tile16(acc, Ak, wbuf + (j % 3) * 16384, u, q);
    }
}

// l1 tile: 64 k-rows x 256 cols fp16; thread (c2 = cols 2c2,2c2+1; rh -> rows rh*4..rh*4+3)
__device__ __forceinline__ void tile64_l1(u64 acc[2][2], const float* __restrict__ Ak,
                                          const __half* __restrict__ buf, int c2, int rh) {
#pragma unroll 8
    for (int kk = 0; kk < 64; kk++) {
        float2 f = __half22float2(*(const __half2*)&buf[kk * 256 + 2 * c2]);
        u64 b0 = pack2(f.x), b1 = pack2(f.y);
        ulonglong2 av = *((const ulonglong2*)(Ak + kk * AST) + rh);
        acc[0][0] = fma2(av.x, b0, acc[0][0]);
        acc[0][1] = fma2(av.x, b1, acc[0][1]);
        acc[1][0] = fma2(av.y, b0, acc[1][0]);
        acc[1][1] = fma2(av.y, b1, acc[1][1]);
    }
}

__device__ __forceinline__ void gemm_pipe_l1(u64 acc[2][2], const __half* W0, const float* A0,
                                             __half* wbuf, unsigned wbuf_s, int c2, int rh, int t) {
    const int NT = 4;
    cp_tile(wbuf_s, W0, t);
    cp_tile(wbuf_s + 32768, W0 + 16384, t);
#pragma unroll 1
    for (int j = 0; j < NT; j++) {
        if (j + 1 < NT) cpwait1(); else cpwait0();
        __syncthreads();
        if (j + 2 < NT) cp_tile(wbuf_s + (unsigned)(((j + 2) % 3) * 32768), W0 + (j + 2) * 16384, t);
        tile64_l1(acc, A0 + j * 64 * AST, wbuf + (j % 3) * 16384, c2, rh);
    }
}

// ---------------- prep ----------------
__global__ void prep_kernel(const float* __restrict__ eWih, const float* __restrict__ eWhh,
                            const float* __restrict__ ebih, const float* __restrict__ ebhh,
                            const float* __restrict__ aW,
                            const float* __restrict__ dWih, const float* __restrict__ dWhh,
                            const float* __restrict__ dbih, const float* __restrict__ dbhh,
                            const float* __restrict__ l1W, const float* __restrict__ l2W) {
    int tid = blockIdx.x * blockDim.x + threadIdx.x;
    int stride = gridDim.x * blockDim.x;
    for (int i = tid; i < 16 * GD; i += stride) {
        int k = i / GD, cc = i % GD, u = cc >> 2, g = cc & 3;
        g_Wh_e_ih[i] = __float2half_rn((k < ID) ? eWih[(g * HD + u) * ID + k] : 0.0f);
    }
    for (int i = tid; i < HD * GD; i += stride) {
        int k = i / GD, cc = i % GD, u = cc >> 2, g = cc & 3;
        g_Wh_e_hh[i] = __float2half_rn(eWhh[(g * HD + u) * HD + k]);
    }
    for (int i = tid; i < GD; i += stride) {
        int u = i >> 2, g = i & 3;
        g_bg_e[i] = ebih[g * HD + u] + ebhh[g * HD + u];
    }
    for (int i = tid; i < KDI * GD; i += stride) {
        int k = i / GD, cc = i % GD, u = cc >> 2, g = cc & 3;
        g_Wh_d_ih[i] = __float2half_rn((k < 262) ? dWih[(g * HD + u) * 262 + k] : 0.0f);
    }
    for (int i = tid; i < HD * GD; i += stride) {
        int k = i / GD, cc = i % GD, u = cc >> 2, g = cc & 3;
        g_Wh_d_hh[i] = __float2half_rn(dWhh[(g * HD + u) * HD + k]);
    }
    for (int i = tid; i < GD; i += stride) {
        int u = i >> 2, g = i & 3;
        g_bg_d[i] = dbih[g * HD + u] + dbhh[g * HD + u];
    }
    for (int i = tid; i < HD * HD; i += stride) {
        int k = i / HD, u = i % HD;
        g_l1Th[i] = __float2half_rn(l1W[u * HD + k]);
    }
    for (int i = tid; i < HD * OD; i += stride) { int k = i / OD, o = i % OD; g_l2T[i] = l2W[o * HD + k]; }
    for (int i = tid; i < 262 * 60; i += stride) {
        int k = i / 60, l = i % 60;
        g_attnT[i] = aW[l * 262 + k];
    }
}

// ---------------- main: one CTA owns 32 batch rows end-to-end ----------------
__global__ void __launch_bounds__(NTH, 1) seq_kernel(const float* __restrict__ x,
                                                     const float* __restrict__ attn_b,
                                                     const float* __restrict__ l1b,
                                                     const float* __restrict__ l2b,
                                                     float* __restrict__ out) {
    extern __shared__ float sm[];
    float*  Ah   = sm;                          // [256*36]  h (f32, [k][row])
    float*  Ain  = Ah + 256 * AST;              // [272*36]  dec input (rows 262..271 zero)
    float*  Ax   = Ain + KDI * AST;             // [16*36]   enc x (rows 6..15 zero)
    __half* wbh  = (__half*)(Ax + 16 * AST);    // [3*16384] fp16 weight tiles (3*32KB)
    float*  s_s  = (float*)((char*)wbh + 3 * 32768); // [32*60] scores
    float*  z_s  = s_s + 32 * 60;               // [256*33]  l1 output [u][r] (scalar access)
    float*  l2T_s = z_s + 256 * 33;             // [256*6]

    const int t  = threadIdx.x;
    const int r0 = blockIdx.x * ROWS;
    const int u  = t & 255;                     // unit (gate cols 4u..4u+3)
    const int q  = t >> 8;                      // row quarter: rows q*8 .. q*8+7
    const unsigned wbuf_s = su32(wbh);

    for (int i = t; i < 256 * AST; i += NTH) Ah[i] = 0.0f;
    for (int i = t; i < 16 * AST; i += NTH) Ax[i] = 0.0f;
    if (t < 32) {
#pragma unroll
        for (int kz = 262; kz < KDI; kz++) Ain[kz * AST + t] = 0.0f;
    }

    float c[8];
#pragma unroll
    for (int i = 0; i < 8; i++) c[i] = 0.0f;
    __syncthreads();

    // ================= encoder =================
    for (int step = 0; step < LEN; step++) {
        if (t < ROWS * ID) {
            int r = t / ID, k = t - r * ID;
            Ax[k * AST + r] = x[(size_t)(r0 + r) * (LEN * ID) + step * ID + k];
        }
        u64 acc[4][4];
        {
            float4 bv = __ldg((const float4*)&g_bg_e[4 * u]);
            u64 q0 = pack2(bv.x), q1 = pack2(bv.y), q2 = pack2(bv.z), q3 = pack2(bv.w);
#pragma unroll
            for (int i = 0; i < 4; i++) { acc[i][0] = q0; acc[i][1] = q1; acc[i][2] = q2; acc[i][3] = q3; }
        }
        gemm_pipe(acc, g_Wh_e_ih, Ax, 1, g_Wh_e_hh, Ah, 16, wbh, wbuf_s, t, u, q);
        __syncthreads();   // all tile computes read Ah before overwrite

        __half* eb = g_ench + (size_t)r0 * (LEN * HD) + (size_t)step * HD + u;
#pragma unroll
        for (int i = 0; i < 4; i++) {
            float2 gi = unpk(acc[i][0]), gf = unpk(acc[i][1]);
            float2 gg = unpk(acc[i][2]), go = unpk(acc[i][3]);
            float ca = sigmf(gf.x) * c[2 * i]     + sigmf(gi.x) * tanhf(gg.x);
            float cb = sigmf(gf.y) * c[2 * i + 1] + sigmf(gi.y) * tanhf(gg.y);
            float ha = sigmf(go.x) * tanhf(ca);
            float hb = sigmf(go.y) * tanhf(cb);
            c[2 * i] = ca; c[2 * i + 1] = cb;
            int rr = q * 8 + 2 * i;
            *(float2*)&Ah[u * AST + rr] = make_float2(ha, hb);
            eb[(size_t)rr * (LEN * HD)]       = __float2half(ha);
            eb[(size_t)(rr + 1) * (LEN * HD)] = __float2half(hb);
        }
        __syncthreads();
    }

    // ================= decoder init =================
#pragma unroll
    for (int i = 0; i < 8; i++) c[i] = 0.0f;
    for (int i = t; i < 256 * 6; i += NTH) l2T_s[i] = g_l2T[i];
    if (t < 32) {
#pragma unroll
        for (int k = 0; k < OD; k++) Ain[k * AST + t] = (k == 4) ? 1.0f : 0.0f;
    }
    const int lA = t & 63, rgp = t >> 6;   // scores: 16 groups of 2 rows
    const u64 abq = pack2((lA < LEN) ? attn_b[lA] : 0.0f);
    const int c2v = t & 127, rhv = t >> 7; // l1: 2 cols, rows rhv*4..rhv*4+3
    const u64 l1bq0 = pack2(l1b[2 * c2v]), l1bq1 = pack2(l1b[2 * c2v + 1]);
    const int rL2 = t / 6, oL2 = t - 6 * (t / 6);
    const float l2bv = (t < ROWS * OD) ? l2b[oL2] : 0.0f;
    __syncthreads();

    // ================= decoder =================
    for (int step = 0; step < TS; step++) {
        // ---- scores: s[r][l] = [h | tok] . attnT[:, l] + b[l]  (attnT from L2)
        if (lA < LEN) {
            u64 sc0 = abq;
#pragma unroll 8
            for (int k = 0; k < HD; k++) {
                u64 w = pack2(__ldg(&g_attnT[k * 60 + lA]));
                sc0 = fma2(((const u64*)(Ah + k * AST))[rgp], w, sc0);
            }
#pragma unroll
            for (int k = 0; k < OD; k++) {
                u64 w = pack2(__ldg(&g_attnT[(HD + k) * 60 + lA]));
                sc0 = fma2(((const u64*)(Ain + k * AST))[rgp], w, sc0);
            }
            float2 f0 = unpk(sc0);
            s_s[(rgp * 2 + 0) * 60 + lA] = f0.x;
            s_s[(rgp * 2 + 1) * 60 + lA] = f0.y;
        }
        __syncthreads();
        // ---- softmax: warp w handles row w
        {
            int w = t >> 5, lane = t & 31;
            float* sp = &s_s[w * 60];
            float v0 = sp[lane];
            float v1 = (lane + 32 < LEN) ? sp[lane + 32] : -1e30f;
            float m = fmaxf(v0, v1);
#pragma unroll
            for (int d = 16; d > 0; d >>= 1) m = fmaxf(m, __shfl_xor_sync(~0u, m, d));
            float e0 = __expf(v0 - m);
            float e1 = (lane + 32 < LEN) ? __expf(v1 - m) : 0.0f;
            float ss = e0 + e1;
#pragma unroll
            for (int d = 16; d > 0; d >>= 1) ss += __shfl_xor_sync(~0u, ss, d);
            float inv = 1.0f / ss;
            sp[lane] = e0 * inv;
            if (lane + 32 < LEN) sp[lane + 32] = e1 * inv;
        }
        __syncthreads();
        // ---- ctx: thread (r = t>>5, 8 h-cols fp16) -> Ain rows 6..261
        {
            int r = t >> 5, c32 = t & 31;
            u64 a8[4];
#pragma unroll
            for (int j = 0; j < 4; j++) a8[j] = 0ULL;
            const __half* ep = g_ench + (size_t)(r0 + r) * (LEN * HD) + c32 * 8;
            const float* apw = &s_s[r * 60];
#pragma unroll 4
            for (int l = 0; l < LEN; l++) {
                u64 aw = pack2(apw[l]);
                uint4 v0 = *(const uint4*)(ep + (size_t)l * HD);
                const unsigned* vv = &v0.x;
#pragma unroll
                for (int j = 0; j < 4; j++) {
                    float2 f = __half22float2(*(const __half2*)&vv[j]);
                    a8[j] = fma2(aw, pkf2(f.x, f.y), a8[j]);
                }
            }
            int kb = 6 + c32 * 8;
#pragma unroll
            for (int j = 0; j < 4; j++) {
                float2 f = unpk(a8[j]);
                Ain[(kb + 2 * j) * AST + r]     = f.x;
                Ain[(kb + 2 * j + 1) * AST + r] = f.y;
            }
        }
        __syncthreads();

        // ---- decoder gates (pipelined ih K=272 + hh K=256, fp16 weights)
        u64 acc[4][4];
        {
            float4 bv = __ldg((const float4*)&g_bg_d[4 * u]);
            u64 q0 = pack2(bv.x), q1 = pack2(bv.y), q2 = pack2(bv.z), q3 = pack2(bv.w);
#pragma unroll
            for (int i = 0; i < 4; i++) { acc[i][0] = q0; acc[i][1] = q1; acc[i][2] = q2; acc[i][3] = q3; }
        }
        gemm_pipe(acc, g_Wh_d_ih, Ain, 17, g_Wh_d_hh, Ah, 16, wbh, wbuf_s, t, u, q);
        __syncthreads();
#pragma unroll
        for (int i = 0; i < 4; i++) {
            float2 gi = unpk(acc[i][0]), gf = unpk(acc[i][1]);
            float2 gg = unpk(acc[i][2]), go = unpk(acc[i][3]);
            float ca = sigmf(gf.x) * c[2 * i]     + sigmf(gi.x) * tanhf(gg.x);
            float cb = sigmf(gf.y) * c[2 * i + 1] + sigmf(gi.y) * tanhf(gg.y);
            float ha = sigmf(go.x) * tanhf(ca);
            float hb = sigmf(go.y) * tanhf(cb);
            c[2 * i] = ca; c[2 * i + 1] = cb;
            *(float2*)&Ah[u * AST + q * 8 + 2 * i] = make_float2(ha, hb);
        }
        __syncthreads();

        // ---- l1 (pipelined, fp16): z = relu(h @ l1T + b1)
        {
            u64 a2[2][2];
            a2[0][0] = l1bq0; a2[0][1] = l1bq1;
            a2[1][0] = l1bq0; a2[1][1] = l1bq1;
            gemm_pipe_l1(a2, g_l1Th, Ah, wbh, wbuf_s, c2v, rhv, t);
#pragma unroll
            for (int i = 0; i < 2; i++) {
                float2 f0 = unpk(a2[i][0]), f1 = unpk(a2[i][1]);
                int rr = rhv * 4 + 2 * i;
                z_s[(2 * c2v) * 33 + rr]     = fmaxf(f0.x, 0.0f);
                z_s[(2 * c2v) * 33 + rr + 1] = fmaxf(f0.y, 0.0f);
                z_s[(2 * c2v + 1) * 33 + rr]     = fmaxf(f1.x, 0.0f);
                z_s[(2 * c2v + 1) * 33 + rr + 1] = fmaxf(f1.y, 0.0f);
            }
        }
        __syncthreads();

        // ---- l2 + output + token feedback (f32 weights)
        if (t < ROWS * OD) {
            float s = l2bv;
#pragma unroll 8
            for (int uu = 0; uu < HD; uu++) s += z_s[uu * 33 + rL2] * l2T_s[uu * 6 + oL2];
            out[(size_t)(r0 + rL2) * (TS * OD) + step * OD + oL2] = s;
            Ain[oL2 * AST + rL2] = s;
        }
        __syncthreads();
    }
}

extern "C" void kernel_launch(void* const* d_in, const int* in_sizes, int n_in,
                              void* d_out, int out_size) {
    const float* x    = (const float*)d_in[0];
    const float* eWih = (const float*)d_in[2];
    const float* eWhh = (const float*)d_in[3];
    const float* ebih = (const float*)d_in[4];
    const float* ebhh = (const float*)d_in[5];
    const float* aW   = (const float*)d_in[6];
    const float* ab   = (const float*)d_in[7];
    const float* dWih = (const float*)d_in[8];
    const float* dWhh = (const float*)d_in[9];
    const float* dbih = (const float*)d_in[10];
    const float* dbhh = (const float*)d_in[11];
    const float* l1W  = (const float*)d_in[12];
    const float* l1b  = (const float*)d_in[13];
    const float* l2W  = (const float*)d_in[14];
    const float* l2b  = (const float*)d_in[15];
    float* out = (float*)d_out;

    prep_kernel<<<256, 256>>>(eWih, eWhh, ebih, ebhh, aW, dWih, dWhh, dbih, dbhh, l1W, l2W);

    const int smem_bytes = (256 * AST + KDI * AST + 16 * AST) * 4   // activations
                         + 3 * 32768                                 // fp16 weight tiles
                         + (32 * 60 + 256 * 33 + 256 * 6) * 4;       // scores + z + l2T
    cudaFuncSetAttribute(seq_kernel, cudaFuncAttributeMaxDynamicSharedMemorySize, smem_bytes);
    seq_kernel<<<NCTA, NTH, smem_bytes>>>(x, ab, l1b, l2b, out);
}

// round 16
// speedup vs baseline: 1.0004x; 1.0004x over previous
#include <cuda_runtime.h>
#include <cuda_fp16.h>

#define BN   4096
#define LEN  60
#define TS   60
#define HD   256
#define ID   6
#define OD   6
#define GD   1024
#define ROWS 32
#define NTH  1024
#define KDI  272         // decoder input K padded to 17 tiles of 16
#define NCTA (BN / ROWS)
#define AST  36          // float stride of activation buffers [k][row]

typedef unsigned long long u64;

// ---------------- device scratch (allocation-free) ----------------
// Gate-interleaved fp16 weights: W[k][u*4+g] = W_orig[g*256+u][k]  (g: 0=i,1=f,2=g,3=o)
__device__ __align__(16) __half g_Wh_e_ih[16 * GD];    // k rows 6..15 zero
__device__ __align__(16) __half g_Wh_e_hh[HD * GD];
__device__ __align__(16) float  g_bg_e[GD];
__device__ __align__(16) __half g_Wh_d_ih[KDI * GD];   // k rows 262..271 zero
__device__ __align__(16) __half g_Wh_d_hh[HD * GD];
__device__ __align__(16) float  g_bg_d[GD];
__device__ __align__(16) __half g_l1Th[HD * HD];       // [k][u]
__device__ __align__(16) float  g_l2T[HD * OD];        // [u][o]  (f32: output layer)
__device__ __align__(16) float  g_attnT[262 * 60];     // [k][l]  (f32)
__device__ __align__(16) __half g_ench[(size_t)BN * LEN * HD];  // encoder outputs fp16

// ---------------- packed fp32x2 helpers ----------------
__device__ __forceinline__ u64 pack2(float v) {
    u64 r; asm("mov.b64 %0, {%1, %1};" : "=l"(r) : "f"(v)); return r;
}
__device__ __forceinline__ u64 pkf2(float a, float b) {
    u64 r; asm("mov.b64 %0, {%1, %2};" : "=l"(r) : "f"(a), "f"(b)); return r;
}
__device__ __forceinline__ u64 fma2(u64 a, u64 b, u64 c) {
    u64 d; asm("fma.rn.f32x2 %0, %1, %2, %3;" : "=l"(d) : "l"(a), "l"(b), "l"(c)); return d;
}
__device__ __forceinline__ float2 unpk(u64 v) {
    float2 f; asm("mov.b64 {%0, %1}, %2;" : "=f"(f.x), "=f"(f.y) : "l"(v)); return f;
}
__device__ __forceinline__ float sigmf(float x) { return 1.0f / (1.0f + __expf(-x)); }

__device__ __forceinline__ unsigned su32(const void* p) {
    unsigned a;
    asm("{ .reg .u64 t; cvta.to.shared.u64 t, %1; cvt.u32.u64 %0, t; }" : "=r"(a) : "l"(p));
    return a;
}
__device__ __forceinline__ void cp16(unsigned d, const void* s) {
    asm volatile("cp.async.cg.shared.global [%0], [%1], 16;" :: "r"(d), "l"(s));
}
__device__ __forceinline__ void cpcommit() { asm volatile("cp.async.commit_group;"); }
__device__ __forceinline__ void cpwait1()  { asm volatile("cp.async.wait_group 1;"); }
__device__ __forceinline__ void cpwait0()  { asm volatile("cp.async.wait_group 0;"); }

// copy one 32KB tile: each of 1024 threads moves 32B
__device__ __forceinline__ void cp_tile(unsigned dst_s, const __half* src, int t) {
    unsigned d = dst_s + (unsigned)(t * 32);
    const char* s = (const char*)src + t * 32;
    cp16(d, s); cp16(d + 16, s + 16);
    cpcommit();
}

// main-gemm tile: 16 k-rows (fp16 weights); thread owns unit u (cols 4u..4u+3), rows q*8..q*8+7
__device__ __forceinline__ void tile16(u64 acc[4][4], const float* __restrict__ Ak,
                                       const __half* __restrict__ buf, int u, int q) {
#pragma unroll
    for (int kk = 0; kk < 16; kk++) {
        const __half2* wp = (const __half2*)&buf[kk * GD + 4 * u];
        __half2 w01 = wp[0], w23 = wp[1];
        float2 f01 = __half22float2(w01), f23 = __half22float2(w23);
        u64 b0 = pack2(f01.x), b1 = pack2(f01.y), b2 = pack2(f23.x), b3 = pack2(f23.y);
        const ulonglong2* ap = (const ulonglong2*)(Ak + kk * AST) + q * 2;
        ulonglong2 a01 = ap[0], a23 = ap[1];
        u64 av0 = a01.x, av1 = a01.y, av2 = a23.x, av3 = a23.y;
        acc[0][0] = fma2(av0, b0, acc[0][0]); acc[0][1] = fma2(av0, b1, acc[0][1]);
        acc[0][2] = fma2(av0, b2, acc[0][2]); acc[0][3] = fma2(av0, b3, acc[0][3]);
        acc[1][0] = fma2(av1, b0, acc[1][0]); acc[1][1] = fma2(av1, b1, acc[1][1]);
        acc[1][2] = fma2(av1, b2, acc[1][2]); acc[1][3] = fma2(av1, b3, acc[1][3]);
        acc[2][0] = fma2(av2, b0, acc[2][0]); acc[2][1] = fma2(av2, b1, acc[2][1]);
        acc[2][2] = fma2(av2, b2, acc[2][2]); acc[2][3] = fma2(av2, b3, acc[2][3]);
        acc[3][0] = fma2(av3, b0, acc[3][0]); acc[3][1] = fma2(av3, b1, acc[3][1]);
        acc[3][2] = fma2(av3, b2, acc[3][2]); acc[3][3] = fma2(av3, b3, acc[3][3]);
    }
}

// two-segment pipelined gemm (tiles of 16 k-rows x 1024 cols fp16, triple-buffered 32KB)
__device__ __forceinline__ void gemm_pipe(u64 acc[4][4],
        const __half* W0, const float* A0, int n0,
        const __half* W1, const float* A1, int n1,
        __half* wbuf, unsigned wbuf_s, int t, int u, int q) {
    const int NT = n0 + n1;
    cp_tile(wbuf_s, W0, t);
    {
        const __half* w1 = (1 < n0) ? (W0 + 16384) : (W1 + (1 - n0) * 16384);
        cp_tile(wbuf_s + 32768, w1, t);
    }
#pragma unroll 1
    for (int j = 0; j < NT; j++) {
        if (j + 1 < NT) cpwait1(); else cpwait0();
        __syncthreads();
        if (j + 2 < NT) {
            int jj = j + 2;
            const __half* ws = (jj < n0) ? (W0 + jj * 16384) : (W1 + (jj - n0) * 16384);
            cp_tile(wbuf_s + (unsigned)((jj % 3) * 32768), ws, t);
        }
        const float* Ak = (j < n0) ? (A0 + j * 16 * AST) : (A1 + (j - n0) * 16 * AST);
        tile16(acc, Ak, wbuf + (j % 3) * 16384, u, q);
    }
}

// l1 tile: 64 k-rows x 256 cols fp16; thread (c2 = cols 2c2,2c2+1; rh -> rows rh*4..rh*4+3)
__device__ __forceinline__ void tile64_l1(u64 acc[2][2], const float* __restrict__ Ak,
                                          const __half* __restrict__ buf, int c2, int rh) {
#pragma unroll 8
    for (int kk = 0; kk < 64; kk++) {
        float2 f = __half22float2(*(const __half2*)&buf[kk * 256 + 2 * c2]);
        u64 b0 = pack2(f.x), b1 = pack2(f.y);
        ulonglong2 av = *((const ulonglong2*)(Ak + kk * AST) + rh);
        acc[0][0] = fma2(av.x, b0, acc[0][0]);
        acc[0][1] = fma2(av.x, b1, acc[0][1]);
        acc[1][0] = fma2(av.y, b0, acc[1][0]);
        acc[1][1] = fma2(av.y, b1, acc[1][1]);
    }
}

__device__ __forceinline__ void gemm_pipe_l1(u64 acc[2][2], const __half* W0, const float* A0,
                                             __half* wbuf, unsigned wbuf_s, int c2, int rh, int t) {
    const int NT = 4;
    cp_tile(wbuf_s, W0, t);
    cp_tile(wbuf_s + 32768, W0 + 16384, t);
#pragma unroll 1
    for (int j = 0; j < NT; j++) {
        if (j + 1 < NT) cpwait1(); else cpwait0();
        __syncthreads();
        if (j + 2 < NT) cp_tile(wbuf_s + (unsigned)(((j + 2) % 3) * 32768), W0 + (j + 2) * 16384, t);
        tile64_l1(acc, A0 + j * 64 * AST, wbuf + (j % 3) * 16384, c2, rh);
    }
}

// ---------------- prep ----------------
__global__ void prep_kernel(const float* __restrict__ eWih, const float* __restrict__ eWhh,
                            const float* __restrict__ ebih, const float* __restrict__ ebhh,
                            const float* __restrict__ aW,
                            const float* __restrict__ dWih, const float* __restrict__ dWhh,
                            const float* __restrict__ dbih, const float* __restrict__ dbhh,
                            const float* __restrict__ l1W, const float* __restrict__ l2W) {
    int tid = blockIdx.x * blockDim.x + threadIdx.x;
    int stride = gridDim.x * blockDim.x;
    for (int i = tid; i < 16 * GD; i += stride) {
        int k = i / GD, cc = i % GD, u = cc >> 2, g = cc & 3;
        g_Wh_e_ih[i] = __float2half_rn((k < ID) ? eWih[(g * HD + u) * ID + k] : 0.0f);
    }
    for (int i = tid; i < HD * GD; i += stride) {
        int k = i / GD, cc = i % GD, u = cc >> 2, g = cc & 3;
        g_Wh_e_hh[i] = __float2half_rn(eWhh[(g * HD + u) * HD + k]);
    }
    for (int i = tid; i < GD; i += stride) {
        int u = i >> 2, g = i & 3;
        g_bg_e[i] = ebih[g * HD + u] + ebhh[g * HD + u];
    }
    for (int i = tid; i < KDI * GD; i += stride) {
        int k = i / GD, cc = i % GD, u = cc >> 2, g = cc & 3;
        g_Wh_d_ih[i] = __float2half_rn((k < 262) ? dWih[(g * HD + u) * 262 + k] : 0.0f);
    }
    for (int i = tid; i < HD * GD; i += stride) {
        int k = i / GD, cc = i % GD, u = cc >> 2, g = cc & 3;
        g_Wh_d_hh[i] = __float2half_rn(dWhh[(g * HD + u) * HD + k]);
    }
    for (int i = tid; i < GD; i += stride) {
        int u = i >> 2, g = i & 3;
        g_bg_d[i] = dbih[g * HD + u] + dbhh[g * HD + u];
    }
    for (int i = tid; i < HD * HD; i += stride) {
        int k = i / HD, u = i % HD;
        g_l1Th[i] = __float2half_rn(l1W[u * HD + k]);
    }
    for (int i = tid; i < HD * OD; i += stride) { int k = i / OD, o = i % OD; g_l2T[i] = l2W[o * HD + k]; }
    for (int i = tid; i < 262 * 60; i += stride) {
        int k = i / 60, l = i % 60;
        g_attnT[i] = aW[l * 262 + k];
    }
}

// ---------------- main: one CTA owns 32 batch rows end-to-end ----------------
__global__ void __launch_bounds__(NTH, 1) seq_kernel(const float* __restrict__ x,
                                                     const float* __restrict__ attn_b,
                                                     const float* __restrict__ l1b,
                                                     const float* __restrict__ l2b,
                                                     float* __restrict__ out) {
    extern __shared__ float sm[];
    float*  Ah   = sm;                          // [256*36]  h (f32, [k][row])
    float*  Ain  = Ah + 256 * AST;              // [272*36]  dec input (rows 262..271 zero)
    float*  Ax   = Ain + KDI * AST;             // [16*36]   enc x (rows 6..15 zero)
    __half* wbh  = (__half*)(Ax + 16 * AST);    // [3*16384] fp16 weight tiles (3*32KB)
    float*  s_s  = (float*)((char*)wbh + 3 * 32768); // [32*60] scores
    float*  z_s  = s_s + 32 * 60;               // [256*33]  l1 output [u][r] (scalar access)
    float*  l2T_s = z_s + 256 * 33;             // [256*6]

    const int t  = threadIdx.x;
    const int r0 = blockIdx.x * ROWS;
    const int u  = t & 255;                     // unit (gate cols 4u..4u+3)
    const int q  = t >> 8;                      // row quarter: rows q*8 .. q*8+7
    const unsigned wbuf_s = su32(wbh);

    for (int i = t; i < 256 * AST; i += NTH) Ah[i] = 0.0f;
    for (int i = t; i < 16 * AST; i += NTH) Ax[i] = 0.0f;
    if (t < 32) {
#pragma unroll
        for (int kz = 262; kz < KDI; kz++) Ain[kz * AST + t] = 0.0f;
    }

    float c[8];
#pragma unroll
    for (int i = 0; i < 8; i++) c[i] = 0.0f;
    __syncthreads();

    // ================= encoder =================
    for (int step = 0; step < LEN; step++) {
        if (t < ROWS * ID) {
            int r = t / ID, k = t - r * ID;
            Ax[k * AST + r] = x[(size_t)(r0 + r) * (LEN * ID) + step * ID + k];
        }
        u64 acc[4][4];
        {
            float4 bv = __ldg((const float4*)&g_bg_e[4 * u]);
            u64 q0 = pack2(bv.x), q1 = pack2(bv.y), q2 = pack2(bv.z), q3 = pack2(bv.w);
#pragma unroll
            for (int i = 0; i < 4; i++) { acc[i][0] = q0; acc[i][1] = q1; acc[i][2] = q2; acc[i][3] = q3; }
        }
        gemm_pipe(acc, g_Wh_e_ih, Ax, 1, g_Wh_e_hh, Ah, 16, wbh, wbuf_s, t, u, q);
        __syncthreads();   // all tile computes read Ah before overwrite

        __half* eb = g_ench + (size_t)r0 * (LEN * HD) + (size_t)step * HD + u;
#pragma unroll
        for (int i = 0; i < 4; i++) {
            float2 gi = unpk(acc[i][0]), gf = unpk(acc[i][1]);
            float2 gg = unpk(acc[i][2]), go = unpk(acc[i][3]);
            float ca = sigmf(gf.x) * c[2 * i]     + sigmf(gi.x) * tanhf(gg.x);
            float cb = sigmf(gf.y) * c[2 * i + 1] + sigmf(gi.y) * tanhf(gg.y);
            float ha = sigmf(go.x) * tanhf(ca);
            float hb = sigmf(go.y) * tanhf(cb);
            c[2 * i] = ca; c[2 * i + 1] = cb;
            int rr = q * 8 + 2 * i;
            *(float2*)&Ah[u * AST + rr] = make_float2(ha, hb);
            eb[(size_t)rr * (LEN * HD)]       = __float2half(ha);
            eb[(size_t)(rr + 1) * (LEN * HD)] = __float2half(hb);
        }
        __syncthreads();
    }

    // ================= decoder init =================
#pragma unroll
    for (int i = 0; i < 8; i++) c[i] = 0.0f;
    for (int i = t; i < 256 * 6; i += NTH) l2T_s[i] = g_l2T[i];
    if (t < 32) {
#pragma unroll
        for (int k = 0; k < OD; k++) Ain[k * AST + t] = (k == 4) ? 1.0f : 0.0f;
    }
    const int lA = t & 63, rgp = t >> 6;   // scores: 16 groups of 2 rows
    const u64 abq = pack2((lA < LEN) ? attn_b[lA] : 0.0f);
    const int c2v = t & 127, rhv = t >> 7; // l1: 2 cols, rows rhv*4..rhv*4+3
    const u64 l1bq0 = pack2(l1b[2 * c2v]), l1bq1 = pack2(l1b[2 * c2v + 1]);
    const int rL2 = t / 6, oL2 = t - 6 * (t / 6);
    const float l2bv = (t < ROWS * OD) ? l2b[oL2] : 0.0f;
    __syncthreads();

    // ================= decoder =================
    for (int step = 0; step < TS; step++) {
        // ---- scores: s[r][l] = [h | tok] . attnT[:, l] + b[l]  (attnT from L2)
        if (lA < LEN) {
            u64 sc0 = abq;
#pragma unroll 8
            for (int k = 0; k < HD; k++) {
                u64 w = pack2(__ldg(&g_attnT[k * 60 + lA]));
                sc0 = fma2(((const u64*)(Ah + k * AST))[rgp], w, sc0);
            }
#pragma unroll
            for (int k = 0; k < OD; k++) {
                u64 w = pack2(__ldg(&g_attnT[(HD + k) * 60 + lA]));
                sc0 = fma2(((const u64*)(Ain + k * AST))[rgp], w, sc0);
            }
            float2 f0 = unpk(sc0);
            s_s[(rgp * 2 + 0) * 60 + lA] = f0.x;
            s_s[(rgp * 2 + 1) * 60 + lA] = f0.y;
        }
        __syncthreads();
        // ---- softmax: warp w handles row w
        {
            int w = t >> 5, lane = t & 31;
            float* sp = &s_s[w * 60];
            float v0 = sp[lane];
            float v1 = (lane + 32 < LEN) ? sp[lane + 32] : -1e30f;
            float m = fmaxf(v0, v1);
#pragma unroll
            for (int d = 16; d > 0; d >>= 1) m = fmaxf(m, __shfl_xor_sync(~0u, m, d));
            float e0 = __expf(v0 - m);
            float e1 = (lane + 32 < LEN) ? __expf(v1 - m) : 0.0f;
            float ss = e0 + e1;
#pragma unroll
            for (int d = 16; d > 0; d >>= 1) ss += __shfl_xor_sync(~0u, ss, d);
            float inv = 1.0f / ss;
            sp[lane] = e0 * inv;
            if (lane + 32 < LEN) sp[lane + 32] = e1 * inv;
        }
        __syncthreads();
        // ---- ctx: thread (r = t>>5, 8 h-cols fp16) -> Ain rows 6..261
        {
            int r = t >> 5, c32 = t & 31;
            u64 a8[4];
#pragma unroll
            for (int j = 0; j < 4; j++) a8[j] = 0ULL;
            const __half* ep = g_ench + (size_t)(r0 + r) * (LEN * HD) + c32 * 8;
            const float* apw = &s_s[r * 60];
#pragma unroll 4
            for (int l = 0; l < LEN; l++) {
                u64 aw = pack2(apw[l]);
                uint4 v0 = *(const uint4*)(ep + (size_t)l * HD);
                const unsigned* vv = &v0.x;
#pragma unroll
                for (int j = 0; j < 4; j++) {
                    float2 f = __half22float2(*(const __half2*)&vv[j]);
                    a8[j] = fma2(aw, pkf2(f.x, f.y), a8[j]);
                }
            }
            int kb = 6 + c32 * 8;
#pragma unroll
            for (int j = 0; j < 4; j++) {
                float2 f = unpk(a8[j]);
                Ain[(kb + 2 * j) * AST + r]     = f.x;
                Ain[(kb + 2 * j + 1) * AST + r] = f.y;
            }
        }
        __syncthreads();

        // ---- decoder gates (pipelined ih K=272 + hh K=256, fp16 weights)
        u64 acc[4][4];
        {
            float4 bv = __ldg((const float4*)&g_bg_d[4 * u]);
            u64 q0 = pack2(bv.x), q1 = pack2(bv.y), q2 = pack2(bv.z), q3 = pack2(bv.w);
#pragma unroll
            for (int i = 0; i < 4; i++) { acc[i][0] = q0; acc[i][1] = q1; acc[i][2] = q2; acc[i][3] = q3; }
        }
        gemm_pipe(acc, g_Wh_d_ih, Ain, 17, g_Wh_d_hh, Ah, 16, wbh, wbuf_s, t, u, q);
        __syncthreads();
#pragma unroll
        for (int i = 0; i < 4; i++) {
            float2 gi = unpk(acc[i][0]), gf = unpk(acc[i][1]);
            float2 gg = unpk(acc[i][2]), go = unpk(acc[i][3]);
            float ca = sigmf(gf.x) * c[2 * i]     + sigmf(gi.x) * tanhf(gg.x);
            float cb = sigmf(gf.y) * c[2 * i + 1] + sigmf(gi.y) * tanhf(gg.y);
            float ha = sigmf(go.x) * tanhf(ca);
            float hb = sigmf(go.y) * tanhf(cb);
            c[2 * i] = ca; c[2 * i + 1] = cb;
            *(float2*)&Ah[u * AST + q * 8 + 2 * i] = make_float2(ha, hb);
        }
        __syncthreads();

        // ---- l1 (pipelined, fp16): z = relu(h @ l1T + b1)
        {
            u64 a2[2][2];
            a2[0][0] = l1bq0; a2[0][1] = l1bq1;
            a2[1][0] = l1bq0; a2[1][1] = l1bq1;
            gemm_pipe_l1(a2, g_l1Th, Ah, wbh, wbuf_s, c2v, rhv, t);
#pragma unroll
            for (int i = 0; i < 2; i++) {
                float2 f0 = unpk(a2[i][0]), f1 = unpk(a2[i][1]);
                int rr = rhv * 4 + 2 * i;
                z_s[(2 * c2v) * 33 + rr]     = fmaxf(f0.x, 0.0f);
                z_s[(2 * c2v) * 33 + rr + 1] = fmaxf(f0.y, 0.0f);
                z_s[(2 * c2v + 1) * 33 + rr]     = fmaxf(f1.x, 0.0f);
                z_s[(2 * c2v + 1) * 33 + rr + 1] = fmaxf(f1.y, 0.0f);
            }
        }
        __syncthreads();

        // ---- l2 + output + token feedback (f32 weights)
        if (t < ROWS * OD) {
            float s = l2bv;
#pragma unroll 8
            for (int uu = 0; uu < HD; uu++) s += z_s[uu * 33 + rL2] * l2T_s[uu * 6 + oL2];
            out[(size_t)(r0 + rL2) * (TS * OD) + step * OD + oL2] = s;
            Ain[oL2 * AST + rL2] = s;
        }
        __syncthreads();
    }
}

extern "C" void kernel_launch(void* const* d_in, const int* in_sizes, int n_in,
                              void* d_out, int out_size) {
    const float* x    = (const float*)d_in[0];
    const float* eWih = (const float*)d_in[2];
    const float* eWhh = (const float*)d_in[3];
    const float* ebih = (const float*)d_in[4];
    const float* ebhh = (const float*)d_in[5];
    const float* aW   = (const float*)d_in[6];
    const float* ab   = (const float*)d_in[7];
    const float* dWih = (const float*)d_in[8];
    const float* dWhh = (const float*)d_in[9];
    const float* dbih = (const float*)d_in[10];
    const float* dbhh = (const float*)d_in[11];
    const float* l1W  = (const float*)d_in[12];
    const float* l1b  = (const float*)d_in[13];
    const float* l2W  = (const float*)d_in[14];
    const float* l2b  = (const float*)d_in[15];
    float* out = (float*)d_out;

    prep_kernel<<<256, 256>>>(eWih, eWhh, ebih, ebhh, aW, dWih, dWhh, dbih, dbhh, l1W, l2W);

    const int smem_bytes = (256 * AST + KDI * AST + 16 * AST) * 4   // activations
                         + 3 * 32768                                 // fp16 weight tiles
                         + (32 * 60 + 256 * 33 + 256 * 6) * 4;       // scores + z + l2T
    cudaFuncSetAttribute(seq_kernel, cudaFuncAttributeMaxDynamicSharedMemorySize, smem_bytes);
    seq_kernel<<<NCTA, NTH, smem_bytes>>>(x, ab, l1b, l2b, out);
}